// round 3
// baseline (speedup 1.0000x reference)
#include <cuda_runtime.h>
#include <cuda_bf16.h>

#define H 1024
#define L 50
#define V 50257
#define NBLK ((V + 7) / 8)   // 6283 blocks for the big matvec

// ---------------- scratch (device globals; no allocation allowed) ----------
__device__ float g_emb[H];        // embedded row
__device__ float g_h0[H];         // initial hidden
__device__ float g_scores[L];     // attention logits
__device__ float g_cat2[2 * H];   // [embedded | attn_applied]
__device__ float g_vec[H];        // comb output (pre-relu GRU input)
__device__ float g_h1[H];         // h after cell 1
__device__ float g_h2[H];         // h after cell 2 (final)
__device__ float g_pm[NBLK + 64]; // per-block partial max
__device__ float g_ps[NBLK + 64]; // per-block partial sum-exp
__device__ float g_lse;

// ---------------- K0: attention scores (one block per l) -------------------
__global__ void __launch_bounds__(256)
k_scores(const int* __restrict__ ids,
         const float* __restrict__ hidden,
         const float* __restrict__ emb,
         const float* __restrict__ attn_w,
         const float* __restrict__ attn_b) {
    int l = blockIdx.x;
    int row = ids[0];
    const float* er = emb + (size_t)row * H;

    if (l == 0) {
        for (int i = threadIdx.x; i < H; i += blockDim.x) {
            g_emb[i] = er[i];
            g_h0[i]  = hidden[i];
        }
    }

    const float* w = attn_w + (size_t)l * 2 * H;
    float acc = 0.f;
    for (int j = threadIdx.x; j < H; j += blockDim.x)
        acc += w[j] * er[j] + w[H + j] * hidden[j];

    __shared__ float red[8];
    #pragma unroll
    for (int o = 16; o; o >>= 1) acc += __shfl_down_sync(0xffffffffu, acc, o);
    if ((threadIdx.x & 31) == 0) red[threadIdx.x >> 5] = acc;
    __syncthreads();
    if (threadIdx.x < 8) {
        float v = red[threadIdx.x];
        #pragma unroll
        for (int o = 4; o; o >>= 1) v += __shfl_down_sync(0xffu, v, o);
        if (threadIdx.x == 0) g_scores[l] = v + attn_b[l];
    }
}

// ---------------- K1: softmax + attn_applied + concat ----------------------
__global__ void __launch_bounds__(256)
k_attn(const float* __restrict__ enc, float* __restrict__ out) {
    __shared__ float aw[64];
    int t = threadIdx.x;
    if (t < 64) aw[t] = (t < L) ? g_scores[t] : -1e30f;
    __syncthreads();
    if (t < 32) {
        float a = aw[t], b = aw[t + 32];
        float m = fmaxf(a, b);
        #pragma unroll
        for (int o = 16; o; o >>= 1) m = fmaxf(m, __shfl_xor_sync(0xffffffffu, m, o));
        float e1 = (t < L) ? __expf(a - m) : 0.f;
        float e2 = (t + 32 < L) ? __expf(b - m) : 0.f;
        float s = e1 + e2;
        #pragma unroll
        for (int o = 16; o; o >>= 1) s += __shfl_xor_sync(0xffffffffu, s, o);
        float inv = 1.f / s;
        aw[t] = e1 * inv;
        aw[t + 32] = e2 * inv;
    }
    __syncthreads();
    if (t < L) out[V + H + t] = aw[t];            // attn_weights output
    for (int i = t; i < H; i += 256) {
        float acc = 0.f;
        #pragma unroll 10
        for (int l = 0; l < L; l++) acc += aw[l] * enc[l * H + i];
        g_cat2[H + i] = acc;
        g_cat2[i] = g_emb[i];
    }
}

// ---------------- K2: comb matvec (warp per row, 2048-dot) -----------------
__global__ void __launch_bounds__(256)
k_comb(const float* __restrict__ comb_w,
       const float* __restrict__ comb_b) {
    __shared__ float sc[2 * H];
    for (int i = threadIdx.x; i < 2 * H; i += blockDim.x) sc[i] = g_cat2[i];
    __syncthreads();
    int warp = threadIdx.x >> 5, lane = threadIdx.x & 31;
    int row = blockIdx.x * 8 + warp;
    const float4* w = (const float4*)(comb_w + (size_t)row * 2 * H);
    float acc = 0.f;
    #pragma unroll
    for (int k = 0; k < 16; k++) {
        int m = lane + k * 32;
        float4 wv = w[m];
        int j = m * 4;
        acc += wv.x * sc[j] + wv.y * sc[j + 1] + wv.z * sc[j + 2] + wv.w * sc[j + 3];
    }
    #pragma unroll
    for (int o = 16; o; o >>= 1) acc += __shfl_down_sync(0xffffffffu, acc, o);
    if (lane == 0) g_vec[row] = acc + comb_b[row];
}

// ---------------- K3: fused GRU cell (warp per output element) -------------
// cell=0: x = relu(g_vec), h = g_h0, dst = g_h1
// cell=1: x = relu(g_h1),  h = g_h1, dst = g_h2
__global__ void __launch_bounds__(256)
k_gru(const float* __restrict__ w_ih,
      const float* __restrict__ w_hh,
      const float* __restrict__ b_ih,
      const float* __restrict__ b_hh,
      int cell) {
    __shared__ float sx[H], sh[H];
    const float* xs = (cell == 0) ? g_vec : g_h1;
    const float* hs = (cell == 0) ? g_h0 : g_h1;
    float* hd = (cell == 0) ? g_h1 : g_h2;
    for (int i = threadIdx.x; i < H; i += blockDim.x) {
        sx[i] = fmaxf(xs[i], 0.f);
        sh[i] = hs[i];
    }
    __syncthreads();
    int warp = threadIdx.x >> 5, lane = threadIdx.x & 31;
    int i = blockIdx.x * 8 + warp;
    float d[6];
    #pragma unroll
    for (int g = 0; g < 3; g++) {
        const float4* wi = (const float4*)(w_ih + (size_t)(g * H + i) * H);
        const float4* wh = (const float4*)(w_hh + (size_t)(g * H + i) * H);
        float ax = 0.f, ah = 0.f;
        #pragma unroll
        for (int k = 0; k < 8; k++) {
            int m = lane + k * 32;
            float4 a = wi[m];
            float4 b = wh[m];
            int j = m * 4;
            ax += a.x * sx[j] + a.y * sx[j + 1] + a.z * sx[j + 2] + a.w * sx[j + 3];
            ah += b.x * sh[j] + b.y * sh[j + 1] + b.z * sh[j + 2] + b.w * sh[j + 3];
        }
        d[2 * g] = ax;
        d[2 * g + 1] = ah;
    }
    #pragma unroll
    for (int g = 0; g < 6; g++) {
        #pragma unroll
        for (int o = 16; o; o >>= 1) d[g] += __shfl_down_sync(0xffffffffu, d[g], o);
    }
    if (lane == 0) {
        float r = 1.f / (1.f + __expf(-(d[0] + b_ih[i] + d[1] + b_hh[i])));
        float z = 1.f / (1.f + __expf(-(d[2] + b_ih[H + i] + d[3] + b_hh[H + i])));
        float n = tanhf(d[4] + b_ih[2 * H + i] + r * (d[5] + b_hh[2 * H + i]));
        hd[i] = (1.f - z) * n + z * sh[i];
    }
}

// ---------------- K4: big matvec out_w @ h + partial logsumexp -------------
__global__ void __launch_bounds__(256)
k_out(const float* __restrict__ out_w,
      const float* __restrict__ out_b,
      float* __restrict__ out) {
    __shared__ float sv[H];
    __shared__ float sm[8];
    for (int i = threadIdx.x; i < H; i += blockDim.x) sv[i] = g_h2[i];
    __syncthreads();
    int warp = threadIdx.x >> 5, lane = threadIdx.x & 31;
    int row = blockIdx.x * 8 + warp;
    float logit = -1e30f;
    if (row < V) {
        const float4* w = (const float4*)(out_w + (size_t)row * H);
        float acc = 0.f;
        #pragma unroll
        for (int k = 0; k < 8; k++) {
            int m = lane + k * 32;
            float4 a = w[m];
            int j = m * 4;
            acc += a.x * sv[j] + a.y * sv[j + 1] + a.z * sv[j + 2] + a.w * sv[j + 3];
        }
        #pragma unroll
        for (int o = 16; o; o >>= 1) acc += __shfl_down_sync(0xffffffffu, acc, o);
        if (lane == 0) {
            logit = acc + out_b[row];
            out[row] = logit;
        }
    }
    if (lane == 0) sm[warp] = logit;
    __syncthreads();
    if (threadIdx.x == 0) {
        float m = -1e30f;
        #pragma unroll
        for (int k = 0; k < 8; k++) m = fmaxf(m, sm[k]);
        float s = 0.f;
        #pragma unroll
        for (int k = 0; k < 8; k++) s += __expf(sm[k] - m);
        g_pm[blockIdx.x] = m;
        g_ps[blockIdx.x] = s;
    }
}

// ---------------- K5: combine partials -> lse; write h output --------------
__global__ void __launch_bounds__(256)
k_lse(float* __restrict__ out) {
    int t = threadIdx.x;
    for (int i = t; i < H; i += 256) out[V + i] = g_h2[i];   // hidden output

    float m = -1e30f, s = 0.f;
    for (int b = t; b < NBLK; b += 256) {
        float bm = g_pm[b], bs = g_ps[b];
        if (bm > m) { s = s * __expf(m - bm) + bs; m = bm; }
        else        { s += bs * __expf(bm - m); }
    }
    __shared__ float rm[8], rs[8];
    #pragma unroll
    for (int o = 16; o; o >>= 1) {
        float om = __shfl_xor_sync(0xffffffffu, m, o);
        float os = __shfl_xor_sync(0xffffffffu, s, o);
        float M = fmaxf(m, om);
        s = s * __expf(m - M) + os * __expf(om - M);
        m = M;
    }
    if ((t & 31) == 0) { rm[t >> 5] = m; rs[t >> 5] = s; }
    __syncthreads();
    if (t < 8) {
        m = rm[t]; s = rs[t];
        #pragma unroll
        for (int o = 4; o; o >>= 1) {
            float om = __shfl_xor_sync(0xffu, m, o);
            float os = __shfl_xor_sync(0xffu, s, o);
            float M = fmaxf(m, om);
            s = s * __expf(m - M) + os * __expf(om - M);
            m = M;
        }
        if (t == 0) g_lse = m + logf(s);
    }
}

// ---------------- K6: normalize log-probs ----------------------------------
__global__ void __launch_bounds__(256)
k_norm(float* __restrict__ out) {
    int v = blockIdx.x * blockDim.x + threadIdx.x;
    if (v < V) out[v] -= g_lse;
}

// ---------------- launch ----------------------------------------------------
extern "C" void kernel_launch(void* const* d_in, const int* in_sizes, int n_in,
                              void* d_out, int out_size) {
    const int*   ids     = (const int*)d_in[0];
    const float* hidden  = (const float*)d_in[1];
    const float* enc     = (const float*)d_in[2];
    const float* emb     = (const float*)d_in[3];
    const float* attn_w  = (const float*)d_in[4];
    const float* attn_b  = (const float*)d_in[5];
    const float* comb_w  = (const float*)d_in[6];
    const float* comb_b  = (const float*)d_in[7];
    const float* w_ih    = (const float*)d_in[8];
    const float* w_hh    = (const float*)d_in[9];
    const float* b_ih    = (const float*)d_in[10];
    const float* b_hh    = (const float*)d_in[11];
    const float* out_w   = (const float*)d_in[12];
    const float* out_b   = (const float*)d_in[13];
    float* out = (float*)d_out;

    k_scores<<<L, 256>>>(ids, hidden, emb, attn_w, attn_b);
    k_attn<<<1, 256>>>(enc, out);
    k_comb<<<H / 8, 256>>>(comb_w, comb_b);
    k_gru<<<H / 8, 256>>>(w_ih, w_hh, b_ih, b_hh, 0);
    k_gru<<<H / 8, 256>>>(w_ih, w_hh, b_ih, b_hh, 1);
    k_out<<<NBLK, 256>>>(out_w, out_b, out);
    k_lse<<<1, 256>>>(out);
    k_norm<<<(V + 255) / 256, 256>>>(out);
}

// round 4
// speedup vs baseline: 1.4267x; 1.4267x over previous
#include <cuda_runtime.h>
#include <cuda_bf16.h>

#define H 1024
#define L 50
#define V 50257
#define NBLK ((V + 7) / 8)   // 6283 blocks for the big matvec

// ---------------- scratch (device globals; no allocation allowed) ----------
__device__ float g_emb[H];        // embedded row
__device__ float g_h0[H];         // initial hidden
__device__ float g_scores[L];     // attention logits
__device__ float g_cat2[2 * H];   // [embedded | attn_applied]
__device__ float g_vec[H];        // comb output (pre-relu GRU input)
__device__ float g_d[6 * H];      // gate dots: [gx_r, gh_r, gx_z, gh_z, gx_n, gh_n]
__device__ float g_h1[H];         // h after cell 1
__device__ float g_h2[H];         // h after cell 2 (final)
__device__ float g_pm[NBLK + 64]; // per-block partial max
__device__ float g_ps[NBLK + 64]; // per-block partial sum-exp
__device__ float g_lse;

// ---------------- K0: attention scores (one block per l) -------------------
__global__ void __launch_bounds__(256)
k_scores(const int* __restrict__ ids,
         const float* __restrict__ hidden,
         const float* __restrict__ emb,
         const float* __restrict__ attn_w,
         const float* __restrict__ attn_b) {
    int l = blockIdx.x;
    int row = ids[0];
    const float* er = emb + (size_t)row * H;

    if (l == 0) {
        for (int i = threadIdx.x; i < H; i += blockDim.x) {
            g_emb[i] = er[i];
            g_h0[i]  = hidden[i];
        }
    }

    const float* w = attn_w + (size_t)l * 2 * H;
    float acc = 0.f;
    for (int j = threadIdx.x; j < H; j += blockDim.x)
        acc += w[j] * er[j] + w[H + j] * hidden[j];

    __shared__ float red[8];
    #pragma unroll
    for (int o = 16; o; o >>= 1) acc += __shfl_down_sync(0xffffffffu, acc, o);
    if ((threadIdx.x & 31) == 0) red[threadIdx.x >> 5] = acc;
    __syncthreads();
    if (threadIdx.x < 8) {
        float v = red[threadIdx.x];
        #pragma unroll
        for (int o = 4; o; o >>= 1) v += __shfl_down_sync(0xffu, v, o);
        if (threadIdx.x == 0) g_scores[l] = v + attn_b[l];
    }
}

// ---------------- K1: softmax + attn_applied + concat (8 blocks) -----------
__global__ void __launch_bounds__(128)
k_attn(const float* __restrict__ enc, float* __restrict__ out) {
    __shared__ float aw[64];
    int t = threadIdx.x;
    if (t < 64) aw[t] = (t < L) ? g_scores[t] : -1e30f;
    __syncthreads();
    if (t < 32) {
        float a = aw[t], b = aw[t + 32];
        float m = fmaxf(a, b);
        #pragma unroll
        for (int o = 16; o; o >>= 1) m = fmaxf(m, __shfl_xor_sync(0xffffffffu, m, o));
        float e1 = (t < L) ? __expf(a - m) : 0.f;
        float e2 = (t + 32 < L) ? __expf(b - m) : 0.f;
        float s = e1 + e2;
        #pragma unroll
        for (int o = 16; o; o >>= 1) s += __shfl_xor_sync(0xffffffffu, s, o);
        float inv = 1.f / s;
        aw[t] = e1 * inv;
        aw[t + 32] = e2 * inv;
    }
    __syncthreads();
    if (blockIdx.x == 0 && t < L) out[V + H + t] = aw[t];   // attn_weights
    int i = blockIdx.x * 128 + t;                           // column slice
    float acc = 0.f;
    #pragma unroll 10
    for (int l = 0; l < L; l++) acc += aw[l] * enc[l * H + i];
    g_cat2[H + i] = acc;
    g_cat2[i] = g_emb[i];
}

// ---------------- K2: comb matvec (2 warps per row, grid=256) --------------
__global__ void __launch_bounds__(256)
k_comb(const float* __restrict__ comb_w,
       const float* __restrict__ comb_b) {
    __shared__ float sc[2 * H];
    __shared__ float part[8];
    for (int i = threadIdx.x; i < 2 * H; i += 256) sc[i] = g_cat2[i];
    __syncthreads();
    int warp = threadIdx.x >> 5, lane = threadIdx.x & 31;
    int row = blockIdx.x * 4 + (warp >> 1);
    int half = warp & 1;
    const float4* w = (const float4*)(comb_w + (size_t)row * 2 * H + half * H);
    float acc = 0.f;
    #pragma unroll
    for (int k = 0; k < 8; k++) {
        int m = lane + k * 32;
        float4 a = w[m];
        int j = half * H + m * 4;
        acc += a.x * sc[j] + a.y * sc[j + 1] + a.z * sc[j + 2] + a.w * sc[j + 3];
    }
    #pragma unroll
    for (int o = 16; o; o >>= 1) acc += __shfl_down_sync(0xffffffffu, acc, o);
    if (lane == 0) part[warp] = acc;
    __syncthreads();
    if (threadIdx.x < 4) {
        int r = blockIdx.x * 4 + threadIdx.x;
        g_vec[r] = part[2 * threadIdx.x] + part[2 * threadIdx.x + 1] + comb_b[r];
    }
}

// ---------------- K3: GRU gate dots — one warp per (matrix,gate,row) -------
// 6144 warps across 768 blocks. Writes dot+bias to g_d[c*H + i] where
// c = 2*gate + (0:ih, 1:hh).
__global__ void __launch_bounds__(256)
k_gates(const float* __restrict__ w_ih, const float* __restrict__ w_hh,
        const float* __restrict__ b_ih, const float* __restrict__ b_hh,
        int cell) {
    __shared__ float sx[H], sh[H];
    const float* xs = (cell == 0) ? g_vec : g_h1;
    const float* hs = (cell == 0) ? g_h0 : g_h1;
    for (int i = threadIdx.x; i < H; i += 256) {
        sx[i] = fmaxf(xs[i], 0.f);   // x = relu(prev output)
        sh[i] = hs[i];
    }
    __syncthreads();
    int warp = threadIdx.x >> 5, lane = threadIdx.x & 31;
    int id = blockIdx.x * 8 + warp;          // 0..6143
    int i = id & (H - 1);
    int c = id >> 10;                        // 0..5
    int gate = c >> 1;
    const float* wmat = (c & 1) ? w_hh : w_ih;
    const float* bias = (c & 1) ? b_hh : b_ih;
    const float* vec  = (c & 1) ? sh : sx;
    const float4* w = (const float4*)(wmat + (size_t)(gate * H + i) * H);
    float acc = 0.f;
    #pragma unroll
    for (int k = 0; k < 8; k++) {
        int m = lane + k * 32;
        float4 a = w[m];
        int j = m * 4;
        acc += a.x * vec[j] + a.y * vec[j + 1] + a.z * vec[j + 2] + a.w * vec[j + 3];
    }
    #pragma unroll
    for (int o = 16; o; o >>= 1) acc += __shfl_down_sync(0xffffffffu, acc, o);
    if (lane == 0) g_d[c * H + i] = acc + bias[gate * H + i];
}

// ---------------- K4: GRU nonlinear combine (1024 threads over 8 blocks) ---
__global__ void __launch_bounds__(128)
k_combine(float* __restrict__ out, int cell) {
    int i = blockIdx.x * 128 + threadIdx.x;
    const float* hold = (cell == 0) ? g_h0 : g_h1;
    float* hnew       = (cell == 0) ? g_h1 : g_h2;
    float r = 1.f / (1.f + __expf(-(g_d[i] + g_d[H + i])));
    float z = 1.f / (1.f + __expf(-(g_d[2 * H + i] + g_d[3 * H + i])));
    float n = tanhf(g_d[4 * H + i] + r * g_d[5 * H + i]);
    float h = (1.f - z) * n + z * hold[i];
    hnew[i] = h;
    if (cell == 1) out[V + i] = h;          // hidden output
}

// ---------------- K5: big matvec out_w @ h + partial logsumexp -------------
__global__ void __launch_bounds__(256)
k_out(const float* __restrict__ out_w,
      const float* __restrict__ out_b,
      float* __restrict__ out) {
    __shared__ float sv[H];
    __shared__ float sm[8];
    for (int i = threadIdx.x; i < H; i += blockDim.x) sv[i] = g_h2[i];
    __syncthreads();
    int warp = threadIdx.x >> 5, lane = threadIdx.x & 31;
    int row = blockIdx.x * 8 + warp;
    float logit = -1e30f;
    if (row < V) {
        const float4* w = (const float4*)(out_w + (size_t)row * H);
        float acc = 0.f;
        #pragma unroll
        for (int k = 0; k < 8; k++) {
            int m = lane + k * 32;
            float4 a = __ldcs(w + m);       // stream: don't pollute L2
            int j = m * 4;
            acc += a.x * sv[j] + a.y * sv[j + 1] + a.z * sv[j + 2] + a.w * sv[j + 3];
        }
        #pragma unroll
        for (int o = 16; o; o >>= 1) acc += __shfl_down_sync(0xffffffffu, acc, o);
        if (lane == 0) {
            logit = acc + out_b[row];
            out[row] = logit;
        }
    }
    if (lane == 0) sm[warp] = logit;
    __syncthreads();
    if (threadIdx.x == 0) {
        float m = -1e30f;
        #pragma unroll
        for (int k = 0; k < 8; k++) m = fmaxf(m, sm[k]);
        float s = 0.f;
        #pragma unroll
        for (int k = 0; k < 8; k++) s += __expf(sm[k] - m);
        g_pm[blockIdx.x] = m;
        g_ps[blockIdx.x] = s;
    }
}

// ---------------- K6: combine partials -> lse ------------------------------
__global__ void __launch_bounds__(256)
k_lse() {
    int t = threadIdx.x;
    float m = -1e30f, s = 0.f;
    for (int b = t; b < NBLK; b += 256) {
        float bm = g_pm[b], bs = g_ps[b];
        if (bm > m) { s = s * __expf(m - bm) + bs; m = bm; }
        else        { s += bs * __expf(bm - m); }
    }
    __shared__ float rm[8], rs[8];
    #pragma unroll
    for (int o = 16; o; o >>= 1) {
        float om = __shfl_xor_sync(0xffffffffu, m, o);
        float os = __shfl_xor_sync(0xffffffffu, s, o);
        float M = fmaxf(m, om);
        s = s * __expf(m - M) + os * __expf(om - M);
        m = M;
    }
    if ((t & 31) == 0) { rm[t >> 5] = m; rs[t >> 5] = s; }
    __syncthreads();
    if (t < 8) {
        m = rm[t]; s = rs[t];
        #pragma unroll
        for (int o = 4; o; o >>= 1) {
            float om = __shfl_xor_sync(0xffu, m, o);
            float os = __shfl_xor_sync(0xffu, s, o);
            float M = fmaxf(m, om);
            s = s * __expf(m - M) + os * __expf(om - M);
            m = M;
        }
        if (t == 0) g_lse = m + logf(s);
    }
}

// ---------------- K7: normalize log-probs ----------------------------------
__global__ void __launch_bounds__(256)
k_norm(float* __restrict__ out) {
    int v = blockIdx.x * blockDim.x + threadIdx.x;
    if (v < V) out[v] -= g_lse;
}

// ---------------- launch ----------------------------------------------------
extern "C" void kernel_launch(void* const* d_in, const int* in_sizes, int n_in,
                              void* d_out, int out_size) {
    const int*   ids     = (const int*)d_in[0];
    const float* hidden  = (const float*)d_in[1];
    const float* enc     = (const float*)d_in[2];
    const float* emb     = (const float*)d_in[3];
    const float* attn_w  = (const float*)d_in[4];
    const float* attn_b  = (const float*)d_in[5];
    const float* comb_w  = (const float*)d_in[6];
    const float* comb_b  = (const float*)d_in[7];
    const float* w_ih    = (const float*)d_in[8];
    const float* w_hh    = (const float*)d_in[9];
    const float* b_ih    = (const float*)d_in[10];
    const float* b_hh    = (const float*)d_in[11];
    const float* out_w   = (const float*)d_in[12];
    const float* out_b   = (const float*)d_in[13];
    float* out = (float*)d_out;

    k_scores<<<L, 256>>>(ids, hidden, emb, attn_w, attn_b);
    k_attn<<<8, 128>>>(enc, out);
    k_comb<<<H / 4, 256>>>(comb_w, comb_b);
    k_gates<<<768, 256>>>(w_ih, w_hh, b_ih, b_hh, 0);
    k_combine<<<8, 128>>>(out, 0);
    k_gates<<<768, 256>>>(w_ih, w_hh, b_ih, b_hh, 1);
    k_combine<<<8, 128>>>(out, 1);
    k_out<<<NBLK, 256>>>(out_w, out_b, out);
    k_lse<<<1, 256>>>();
    k_norm<<<(V + 255) / 256, 256>>>(out);
}